// round 15
// baseline (speedup 1.0000x reference)
#include <cuda_runtime.h>

#define Bsz 128
#define Tsz 2048
#define Fsz 64
#define Usz 128
#define G4  512          // 4*U
#define CH  512          // time-chunk length
#define NCH (Tsz / CH)   // 4 chunks
#define TB1 (CH / 8)     // 64 xw1 t-blocks per chunk (8 t per unit)
#define TB2 (CH / 16)    // 32 xw2 t-blocks per chunk (16 t per unit)

// Chunked scratch, b-major layouts. ~290 MB total.
__device__ float g_xw1c[(size_t)Bsz * CH * G4];   // 128 MB: [b][tc][512]
__device__ float g_h1c [(size_t)Bsz * CH * Usz];  // 32 MB:  [b][tc][128]
__device__ float g_xw2c[(size_t)Bsz * CH * G4];   // 128 MB: [b][tc][512]
// Carried recurrent state (h,c per layer), [b][u]
__device__ float g_h1s[Bsz * Usz];
__device__ float g_c1s[Bsz * Usz];
__device__ float g_h2s[Bsz * Usz];
__device__ float g_c2s[Bsz * Usz];

__device__ __forceinline__ float sigmoidf(float x) {
    return __fdividef(1.0f, 1.0f + __expf(-x));
}

// ---- packed f32x2 helpers (Blackwell) -------------------------------------
__device__ __forceinline__ unsigned long long pk2(float lo, float hi) {
    unsigned long long r;
    asm("mov.b64 %0, {%1, %2};" : "=l"(r) : "f"(lo), "f"(hi));
    return r;
}
__device__ __forceinline__ void ffma2(unsigned long long& acc,
                                      unsigned long long a,
                                      unsigned long long b) {
    asm("fma.rn.f32x2 %0, %1, %2, %0;" : "+l"(acc) : "l"(a), "l"(b));
}
__device__ __forceinline__ float hsum2(unsigned long long a) {
    float lo, hi;
    asm("mov.b64 {%0, %1}, %2;" : "=f"(lo), "=f"(hi) : "l"(a));
    return lo + hi;
}
__device__ __forceinline__ unsigned long long add2(unsigned long long a,
                                                   unsigned long long b) {
    unsigned long long r;
    asm("add.rn.f32x2 %0, %1, %2;" : "=l"(r) : "l"(a), "l"(b));
    return r;
}
__device__ __forceinline__ float2 unpk2(unsigned long long a) {
    float lo, hi;
    asm("mov.b64 {%0, %1}, %2;" : "=f"(lo), "=f"(hi) : "l"(a));
    return make_float2(lo, hi);
}

// ---------------------------------------------------------------------------
// k_xw1 (f32x2): unchanged from round 12.
// ---------------------------------------------------------------------------
#define XW1_FREG 40                     // f rows in registers
#define XW1_FSMP ((Fsz - XW1_FREG) / 2) // 12 smem f-pairs

__global__ __launch_bounds__(256, 2) void k_xw1(const float* __restrict__ x,
                                                const float* __restrict__ W1,
                                                const float* __restrict__ b1,
                                                int t0) {
    extern __shared__ double2 sm1[];
    double2* w1s = sm1;                    // [12 f-pairs][256 g] = 48 KB
    double2* xs2 = sm1 + XW1_FSMP * 256;   // [8 t][32 f-pairs] = 4 KB
    float2* xs2f = (float2*)xs2;

    const int g = threadIdx.x;
    unsigned long long wr[XW1_FREG];
#pragma unroll
    for (int f = 0; f < XW1_FREG; f++)
        wr[f] = pk2(W1[f * G4 + 2 * g], W1[f * G4 + 2 * g + 1]);
    for (int p = 0; p < XW1_FSMP; p++) {
        int fs = XW1_FREG + 2 * p;
        unsigned long long w0 = pk2(W1[fs * G4 + 2 * g], W1[fs * G4 + 2 * g + 1]);
        unsigned long long w1 = pk2(W1[(fs + 1) * G4 + 2 * g], W1[(fs + 1) * G4 + 2 * g + 1]);
        w1s[p * 256 + g] = make_double2(__longlong_as_double(w0), __longlong_as_double(w1));
    }
    const unsigned long long biasp = pk2(b1[2 * g], b1[2 * g + 1]);
    __syncthreads();

    const int nunits = Bsz * TB1;            // 8192
    float v0 = 0.0f, v1 = 0.0f;
    {
        int unit = blockIdx.x;
        if (unit < nunits) {
            int b = unit / TB1, tb = unit % TB1;
            const float* src = &x[((size_t)b * Tsz + t0 + tb * 8) * Fsz];
            v0 = src[g];
            v1 = src[256 + g];
        }
    }

    for (int unit = blockIdx.x; unit < nunits; unit += gridDim.x) {
        xs2f[g]       = make_float2(v0, v0);
        xs2f[256 + g] = make_float2(v1, v1);
        __syncthreads();

        int nu = unit + gridDim.x;
        if (nu < nunits) {
            int b = nu / TB1, tb = nu % TB1;
            const float* src = &x[((size_t)b * Tsz + t0 + tb * 8) * Fsz];
            v0 = src[g];
            v1 = src[256 + g];
        }

        unsigned long long acc[8];
#pragma unroll
        for (int r = 0; r < 8; r++) acc[r] = biasp;
#pragma unroll 5
        for (int f2 = 0; f2 < XW1_FREG / 2; f2++) {
#pragma unroll
            for (int r = 0; r < 8; r++) {
                double2 d2 = xs2[r * 32 + f2];
                ffma2(acc[r], __double_as_longlong(d2.x), wr[2 * f2]);
                ffma2(acc[r], __double_as_longlong(d2.y), wr[2 * f2 + 1]);
            }
        }
#pragma unroll 4
        for (int p = 0; p < XW1_FSMP; p++) {
            double2 w = w1s[p * 256 + g];
            unsigned long long w0 = __double_as_longlong(w.x);
            unsigned long long w1 = __double_as_longlong(w.y);
#pragma unroll
            for (int r = 0; r < 8; r++) {
                double2 d2 = xs2[r * 32 + XW1_FREG / 2 + p];
                ffma2(acc[r], __double_as_longlong(d2.x), w0);
                ffma2(acc[r], __double_as_longlong(d2.y), w1);
            }
        }
        {
            int b = unit / TB1, tb = unit % TB1;
            float* dst = &g_xw1c[((size_t)b * CH + tb * 8) * G4];
#pragma unroll
            for (int r = 0; r < 8; r++)
                *(float2*)&dst[(size_t)r * G4 + 2 * g] = unpk2(acc[r]);
        }
        __syncthreads();
    }
}

// ---------------------------------------------------------------------------
// k_xw2 (f32x2): unchanged from round 12.
// ---------------------------------------------------------------------------
__global__ __launch_bounds__(256, 1) void k_xw2(const float* __restrict__ W2,
                                                const float* __restrict__ b2) {
    extern __shared__ double2 smx[];
    double2* w2s  = smx;                 // [32 f-pairs][256 g] = 128 KB
    double2* xdup = smx + 32 * 256;      // [16 t][64 f-pairs] = 16 KB
    float2* xdupf = (float2*)xdup;

    const int g = threadIdx.x;
    unsigned long long wr[64];
#pragma unroll
    for (int f = 0; f < 64; f++)
        wr[f] = pk2(W2[f * G4 + 2 * g], W2[f * G4 + 2 * g + 1]);
    for (int p = 0; p < 32; p++) {
        int fs = 64 + 2 * p;
        unsigned long long w0 = pk2(W2[fs * G4 + 2 * g], W2[fs * G4 + 2 * g + 1]);
        unsigned long long w1 = pk2(W2[(fs + 1) * G4 + 2 * g], W2[(fs + 1) * G4 + 2 * g + 1]);
        w2s[p * 256 + g] = make_double2(__longlong_as_double(w0), __longlong_as_double(w1));
    }
    const unsigned long long biasp = pk2(b2[2 * g], b2[2 * g + 1]);
    __syncthreads();

    const int nunits = Bsz * TB2;            // 4096
    float v[8];
#pragma unroll
    for (int j = 0; j < 8; j++) v[j] = 0.0f;
    {
        int unit = blockIdx.x;
        if (unit < nunits) {
            int b = unit / TB2, tb = unit % TB2;
            const float* src = &g_h1c[((size_t)b * CH + tb * 16) * Usz];
#pragma unroll
            for (int j = 0; j < 8; j++) v[j] = src[j * 256 + g];
        }
    }

    for (int unit = blockIdx.x; unit < nunits; unit += gridDim.x) {
#pragma unroll
        for (int j = 0; j < 8; j++)
            xdupf[j * 256 + g] = make_float2(v[j], v[j]);
        __syncthreads();

        int nu = unit + gridDim.x;
        if (nu < nunits) {
            int b = nu / TB2, tb = nu % TB2;
            const float* src = &g_h1c[((size_t)b * CH + tb * 16) * Usz];
#pragma unroll
            for (int j = 0; j < 8; j++) v[j] = src[j * 256 + g];
        }

        unsigned long long acc[16];
#pragma unroll
        for (int r = 0; r < 16; r++) acc[r] = biasp;
#pragma unroll 4
        for (int f2 = 0; f2 < 32; f2++) {
#pragma unroll
            for (int r = 0; r < 16; r++) {
                double2 d2 = xdup[r * 64 + f2];
                ffma2(acc[r], __double_as_longlong(d2.x), wr[2 * f2]);
                ffma2(acc[r], __double_as_longlong(d2.y), wr[2 * f2 + 1]);
            }
        }
#pragma unroll 4
        for (int p = 0; p < 32; p++) {
            double2 w = w2s[p * 256 + g];
            unsigned long long w0 = __double_as_longlong(w.x);
            unsigned long long w1 = __double_as_longlong(w.y);
#pragma unroll
            for (int r = 0; r < 16; r++) {
                double2 d2 = xdup[r * 64 + 32 + p];
                ffma2(acc[r], __double_as_longlong(d2.x), w0);
                ffma2(acc[r], __double_as_longlong(d2.y), w1);
            }
        }
        {
            int b = unit / TB2, tb = unit % TB2;
            float* dst = &g_xw2c[((size_t)b * CH + tb * 16) * G4];
#pragma unroll
            for (int r = 0; r < 16; r++)
                *(float2*)&dst[(size_t)r * G4 + 2 * g] = unpk2(acc[r]);
        }
        __syncthreads();
    }
}

// ---------------------------------------------------------------------------
// Recurrent kernel: TWO batches per CTA, round-12 gate structure.
// grid 64, 256 threads. Thread g owns cols (2g, 2g+1) for batches
// (2*blk, 2*blk+1). Weight reads (regs + smem) are shared across both
// batches -> 8 independent FFMA2 chains per thread fill latency stalls.
// Gate phase: t<128 -> batch0 unit t; t>=128 -> batch1 unit t-128.
// ---------------------------------------------------------------------------
#define RREC 72              // rows in registers
#define RPAIR (RREC / 2)     // 36 packed pairs
#define RSMM (Usz - RREC)    // 56 rows in smem
#define SPAIR (RSMM / 2)     // 28 packed pairs

template <bool LAYER1>
__global__ __launch_bounds__(256, 1) void lstm_rec(const float* __restrict__ Uw,
                                                   const float* __restrict__ Wd,
                                                   const float* __restrict__ bd,
                                                   float* __restrict__ out,
                                                   int first, int last) {
    extern __shared__ float sm[];
    float* ws   = sm;                          // SPAIR*1024 floats (~112 KB)
    float* hbuf = sm + SPAIR * 1024;           // 256 floats: [0:128)=b0, [128:256)=b1
    float* zbuf = hbuf + 256;                  // 1024 floats: [0:512)=b0, [512:1024)=b1

    const int g = threadIdx.x;                 // owns cols 2g, 2g+1 (both batches)
    const int b0 = 2 * blockIdx.x;
    const int b1 = b0 + 1;
    const int gate = g >> 6;                   // 0:i 1:f 2:g(relu) 3:o
    const float* __restrict__ xwb =
        (LAYER1 ? (const float*)g_xw1c : (const float*)g_xw2c);
    const float* __restrict__ xw0 = xwb + (size_t)b0 * CH * G4;
    const float* __restrict__ xw1 = xwb + (size_t)b1 * CH * G4;
    float* __restrict__ hs = LAYER1 ? g_h1s : g_h2s;
    float* __restrict__ cs = LAYER1 ? g_c1s : g_c2s;

    // Register weights: rows 0..RREC-1 packed by row pairs (shared by batches).
    unsigned long long wrA[RPAIR], wrB[RPAIR];
#pragma unroll
    for (int p = 0; p < RPAIR; p++) {
        wrA[p] = pk2(Uw[(2 * p) * G4 + 2 * g],     Uw[(2 * p + 1) * G4 + 2 * g]);
        wrB[p] = pk2(Uw[(2 * p) * G4 + 2 * g + 1], Uw[(2 * p + 1) * G4 + 2 * g + 1]);
    }
    // Smem weights: rows RREC..127, packed (wA_r0, wA_r1, wB_r0, wB_r1).
    for (int i = g; i < SPAIR * 256; i += 256) {
        int p = i >> 8, q = i & 255;
        int r0 = RREC + 2 * p;
        ((float4*)ws)[i] = make_float4(Uw[r0 * G4 + 2 * q], Uw[(r0 + 1) * G4 + 2 * q],
                                       Uw[r0 * G4 + 2 * q + 1], Uw[(r0 + 1) * G4 + 2 * q + 1]);
    }

    // State: thread t<128 owns batch0 unit t; t>=128 owns batch1 unit t-128.
    float c = 0.0f;
    {
        int mb = (g < 128) ? b0 : b1;
        int u  = g & 127;
        hbuf[g] = first ? 0.0f : hs[mb * Usz + u];
        if (!first) c = cs[mb * Usz + u];
    }
    __syncthreads();

    float2 cur0 = *(const float2*)&xw0[2 * g];   // tc = 0
    float2 cur1 = *(const float2*)&xw1[2 * g];

    const double2* hb20 = (const double2*)hbuf;          // batch0 h row-quads
    const double2* hb21 = (const double2*)(hbuf + 128);  // batch1
    const double2* wsd  = (const double2*)ws;

    for (int tc = 0; tc < CH; tc++) {
        float2 nxt0 = make_float2(0.0f, 0.0f), nxt1 = make_float2(0.0f, 0.0f);
        if (tc + 1 < CH) {
            nxt0 = *(const float2*)&xw0[(size_t)(tc + 1) * G4 + 2 * g];
            nxt1 = *(const float2*)&xw1[(size_t)(tc + 1) * G4 + 2 * g];
        }

        unsigned long long a0A0 = 0ull, a0A1 = 0ull, a0B0 = 0ull, a0B1 = 0ull;
        unsigned long long a1A0 = 0ull, a1A1 = 0ull, a1B0 = 0ull, a1B1 = 0ull;
        // rows 0..RREC-1 (register weights, shared across batches)
#pragma unroll
        for (int k = 0; k < RPAIR / 2; k++) {
            double2 hd0 = hb20[k];
            double2 hd1 = hb21[k];
            unsigned long long h001 = __double_as_longlong(hd0.x);
            unsigned long long h023 = __double_as_longlong(hd0.y);
            unsigned long long h101 = __double_as_longlong(hd1.x);
            unsigned long long h123 = __double_as_longlong(hd1.y);
            ffma2(a0A0, h001, wrA[2 * k]);
            ffma2(a0B0, h001, wrB[2 * k]);
            ffma2(a1A0, h101, wrA[2 * k]);
            ffma2(a1B0, h101, wrB[2 * k]);
            ffma2(a0A1, h023, wrA[2 * k + 1]);
            ffma2(a0B1, h023, wrB[2 * k + 1]);
            ffma2(a1A1, h123, wrA[2 * k + 1]);
            ffma2(a1B1, h123, wrB[2 * k + 1]);
        }
        // rows RREC..127 (smem weights, read once, used for both batches)
#pragma unroll
        for (int k = 0; k < SPAIR / 2; k++) {
            double2 hd0 = hb20[RPAIR / 2 + k];
            double2 hd1 = hb21[RPAIR / 2 + k];
            unsigned long long h001 = __double_as_longlong(hd0.x);
            unsigned long long h023 = __double_as_longlong(hd0.y);
            unsigned long long h101 = __double_as_longlong(hd1.x);
            unsigned long long h123 = __double_as_longlong(hd1.y);
            double2 w0 = wsd[(2 * k) * 256 + g];
            double2 w1 = wsd[(2 * k + 1) * 256 + g];
            unsigned long long w0A = __double_as_longlong(w0.x);
            unsigned long long w0B = __double_as_longlong(w0.y);
            unsigned long long w1A = __double_as_longlong(w1.x);
            unsigned long long w1B = __double_as_longlong(w1.y);
            ffma2(a0A0, h001, w0A);
            ffma2(a0B0, h001, w0B);
            ffma2(a1A0, h101, w0A);
            ffma2(a1B0, h101, w0B);
            ffma2(a0A1, h023, w1A);
            ffma2(a0B1, h023, w1B);
            ffma2(a1A1, h123, w1A);
            ffma2(a1B1, h123, w1B);
        }
        float zA0 = cur0.x + hsum2(add2(a0A0, a0A1));
        float zB0 = cur0.y + hsum2(add2(a0B0, a0B1));
        float zA1 = cur1.x + hsum2(add2(a1A0, a1A1));
        float zB1 = cur1.y + hsum2(add2(a1B0, a1B1));
        if (gate == 2) {
            zA0 = fmaxf(zA0, 0.0f); zB0 = fmaxf(zB0, 0.0f);
            zA1 = fmaxf(zA1, 0.0f); zB1 = fmaxf(zB1, 0.0f);
        } else {
            zA0 = sigmoidf(zA0); zB0 = sigmoidf(zB0);
            zA1 = sigmoidf(zA1); zB1 = sigmoidf(zB1);
        }
        *(float2*)&zbuf[2 * g]       = make_float2(zA0, zB0);
        *(float2*)&zbuf[512 + 2 * g] = make_float2(zA1, zB1);
        __syncthreads();

        // Gate phase: all 256 threads active.
        {
            const float* zb = (g < 128) ? zbuf : (zbuf + 512);
            int u = g & 127;
            float ig = zb[u];
            float fg = zb[128 + u];
            float gg = zb[256 + u];
            float og = zb[384 + u];
            c = fg * c + ig * gg;
            float h = og * fmaxf(c, 0.0f);
            hbuf[g] = h;
            if (LAYER1) {
                int mb = (g < 128) ? b0 : b1;
                g_h1c[((size_t)mb * CH + tc) * Usz + u] = h;
            }
        }
        __syncthreads();
        cur0 = nxt0;
        cur1 = nxt1;
    }

    // Persist state
    {
        int mb = (g < 128) ? b0 : b1;
        int u  = g & 127;
        hs[mb * Usz + u] = hbuf[g];
        cs[mb * Usz + u] = c;
    }

    if (!LAYER1 && last) {
        // Final dense: out[b] = sum_u h[u]*Wd[u] + bd
        zbuf[g] = hbuf[g] * Wd[g & 127];
        __syncthreads();
        if (g == 0) {
            float s = bd[0];
#pragma unroll 8
            for (int i = 0; i < Usz; i++) s += zbuf[i];
            out[b0] = s;
        }
        if (g == 1) {
            float s = bd[0];
#pragma unroll 8
            for (int i = 0; i < Usz; i++) s += zbuf[128 + i];
            out[b1] = s;
        }
    }
}

// ---------------------------------------------------------------------------
extern "C" void kernel_launch(void* const* d_in, const int* in_sizes, int n_in,
                              void* d_out, int out_size) {
    const float* x  = (const float*)d_in[0];
    const float* W1 = (const float*)d_in[1];
    const float* U1 = (const float*)d_in[2];
    const float* b1 = (const float*)d_in[3];
    const float* W2 = (const float*)d_in[4];
    const float* U2 = (const float*)d_in[5];
    const float* b2 = (const float*)d_in[6];
    const float* Wd = (const float*)d_in[7];
    const float* bd = (const float*)d_in[8];
    float* out = (float*)d_out;

    const size_t sm_xw1 = (size_t)(XW1_FSMP * 256 + 8 * 32) * sizeof(double2);  // 52 KB
    const size_t sm_xw2 = (size_t)(32 * 256 + 16 * 64) * sizeof(double2);       // 144 KB
    const size_t sm_rec = (size_t)(SPAIR * 1024 + 256 + 1024) * sizeof(float);  // ~117 KB

    (void)cudaFuncSetAttribute((const void*)k_xw1,
                         cudaFuncAttributeMaxDynamicSharedMemorySize, (int)sm_xw1);
    (void)cudaFuncSetAttribute((const void*)k_xw2,
                         cudaFuncAttributeMaxDynamicSharedMemorySize, (int)sm_xw2);
    (void)cudaFuncSetAttribute((const void*)lstm_rec<true>,
                         cudaFuncAttributeMaxDynamicSharedMemorySize, (int)sm_rec);
    (void)cudaFuncSetAttribute((const void*)lstm_rec<false>,
                         cudaFuncAttributeMaxDynamicSharedMemorySize, (int)sm_rec);

    for (int k = 0; k < NCH; k++) {
        const int first = (k == 0);
        const int last  = (k == NCH - 1);
        k_xw1<<<296, 256, sm_xw1>>>(x, W1, b1, k * CH);
        lstm_rec<true><<<Bsz / 2, 256, sm_rec>>>(U1, Wd, bd, out, first, last);
        k_xw2<<<148, 256, sm_xw2>>>(W2, b2);
        lstm_rec<false><<<Bsz / 2, 256, sm_rec>>>(U2, Wd, bd, out, first, last);
    }
}

// round 16
// speedup vs baseline: 1.3419x; 1.3419x over previous
#include <cuda_runtime.h>

#define Bsz 128
#define Tsz 2048
#define Fsz 64
#define Usz 128
#define G4  512          // 4*U
#define CH  1024         // time-chunk length
#define NCH (Tsz / CH)   // 2 chunks
#define TB1 (CH / 8)     // 128 xw1 t-blocks per chunk (8 t per unit)
#define TB2 (CH / 16)    // 64 xw2 t-blocks per chunk (16 t per unit)

// Chunked scratch, b-major layouts. ~580 MB total.
__device__ float g_xw1c[(size_t)Bsz * CH * G4];   // 256 MB: [b][tc][512]
__device__ float g_h1c [(size_t)Bsz * CH * Usz];  // 64 MB:  [b][tc][128]
__device__ float g_xw2c[(size_t)Bsz * CH * G4];   // 256 MB: [b][tc][512]
// Carried recurrent state (h,c per layer), [b][u]
__device__ float g_h1s[Bsz * Usz];
__device__ float g_c1s[Bsz * Usz];
__device__ float g_h2s[Bsz * Usz];
__device__ float g_c2s[Bsz * Usz];

__device__ __forceinline__ float sigmoidf(float x) {
    return __fdividef(1.0f, 1.0f + __expf(-x));
}

// ---- packed f32x2 helpers (Blackwell) -------------------------------------
__device__ __forceinline__ unsigned long long pk2(float lo, float hi) {
    unsigned long long r;
    asm("mov.b64 %0, {%1, %2};" : "=l"(r) : "f"(lo), "f"(hi));
    return r;
}
__device__ __forceinline__ void ffma2(unsigned long long& acc,
                                      unsigned long long a,
                                      unsigned long long b) {
    asm("fma.rn.f32x2 %0, %1, %2, %0;" : "+l"(acc) : "l"(a), "l"(b));
}
__device__ __forceinline__ float hsum2(unsigned long long a) {
    float lo, hi;
    asm("mov.b64 {%0, %1}, %2;" : "=f"(lo), "=f"(hi) : "l"(a));
    return lo + hi;
}
__device__ __forceinline__ unsigned long long add2(unsigned long long a,
                                                   unsigned long long b) {
    unsigned long long r;
    asm("add.rn.f32x2 %0, %1, %2;" : "=l"(r) : "l"(a), "l"(b));
    return r;
}
__device__ __forceinline__ float2 unpk2(unsigned long long a) {
    float lo, hi;
    asm("mov.b64 {%0, %1}, %2;" : "=f"(lo), "=f"(hi) : "l"(a));
    return make_float2(lo, hi);
}

// ---------------------------------------------------------------------------
// k_xw1 (f32x2): unit = (b, 8 consecutive t). 256 threads own col pairs
// (2g, 2g+1). Weights: f 0..39 in regs, f 40..63 in smem -> ~125 regs,
// 2 CTAs/SM for latency hiding. x fill contiguous, prefetched one unit ahead.
// ---------------------------------------------------------------------------
#define XW1_FREG 40                     // f rows in registers
#define XW1_FSMP ((Fsz - XW1_FREG) / 2) // 12 smem f-pairs

__global__ __launch_bounds__(256, 2) void k_xw1(const float* __restrict__ x,
                                                const float* __restrict__ W1,
                                                const float* __restrict__ b1,
                                                int t0) {
    extern __shared__ double2 sm1[];
    double2* w1s = sm1;                    // [12 f-pairs][256 g] = 48 KB
    double2* xs2 = sm1 + XW1_FSMP * 256;   // [8 t][32 f-pairs] = 4 KB
    float2* xs2f = (float2*)xs2;

    const int g = threadIdx.x;
    unsigned long long wr[XW1_FREG];
#pragma unroll
    for (int f = 0; f < XW1_FREG; f++)
        wr[f] = pk2(W1[f * G4 + 2 * g], W1[f * G4 + 2 * g + 1]);
    for (int p = 0; p < XW1_FSMP; p++) {
        int fs = XW1_FREG + 2 * p;
        unsigned long long w0 = pk2(W1[fs * G4 + 2 * g], W1[fs * G4 + 2 * g + 1]);
        unsigned long long w1 = pk2(W1[(fs + 1) * G4 + 2 * g], W1[(fs + 1) * G4 + 2 * g + 1]);
        w1s[p * 256 + g] = make_double2(__longlong_as_double(w0), __longlong_as_double(w1));
    }
    const unsigned long long biasp = pk2(b1[2 * g], b1[2 * g + 1]);
    __syncthreads();

    const int nunits = Bsz * TB1;            // 16384
    float v0 = 0.0f, v1 = 0.0f;
    {
        int unit = blockIdx.x;
        if (unit < nunits) {
            int b = unit / TB1, tb = unit % TB1;
            const float* src = &x[((size_t)b * Tsz + t0 + tb * 8) * Fsz];
            v0 = src[g];
            v1 = src[256 + g];
        }
    }

    for (int unit = blockIdx.x; unit < nunits; unit += gridDim.x) {
        xs2f[g]       = make_float2(v0, v0);
        xs2f[256 + g] = make_float2(v1, v1);
        __syncthreads();

        int nu = unit + gridDim.x;
        if (nu < nunits) {
            int b = nu / TB1, tb = nu % TB1;
            const float* src = &x[((size_t)b * Tsz + t0 + tb * 8) * Fsz];
            v0 = src[g];
            v1 = src[256 + g];
        }

        unsigned long long acc[8];
#pragma unroll
        for (int r = 0; r < 8; r++) acc[r] = biasp;
#pragma unroll 5
        for (int f2 = 0; f2 < XW1_FREG / 2; f2++) {
#pragma unroll
            for (int r = 0; r < 8; r++) {
                double2 d2 = xs2[r * 32 + f2];
                ffma2(acc[r], __double_as_longlong(d2.x), wr[2 * f2]);
                ffma2(acc[r], __double_as_longlong(d2.y), wr[2 * f2 + 1]);
            }
        }
#pragma unroll 4
        for (int p = 0; p < XW1_FSMP; p++) {
            double2 w = w1s[p * 256 + g];
            unsigned long long w0 = __double_as_longlong(w.x);
            unsigned long long w1 = __double_as_longlong(w.y);
#pragma unroll
            for (int r = 0; r < 8; r++) {
                double2 d2 = xs2[r * 32 + XW1_FREG / 2 + p];
                ffma2(acc[r], __double_as_longlong(d2.x), w0);
                ffma2(acc[r], __double_as_longlong(d2.y), w1);
            }
        }
        {
            int b = unit / TB1, tb = unit % TB1;
            float* dst = &g_xw1c[((size_t)b * CH + tb * 8) * G4];
#pragma unroll
            for (int r = 0; r < 8; r++)
                *(float2*)&dst[(size_t)r * G4 + 2 * g] = unpk2(acc[r]);
        }
        __syncthreads();
    }
}

// ---------------------------------------------------------------------------
// k_xw2 (f32x2): unit = (b, 16 consecutive t). 16 acc chains per thread so
// each smem weight read feeds 16 rows. K=128: f 0..63 in regs, f 64..127 in
// smem (packed double2). h1 fill contiguous, prefetched one unit ahead.
// ---------------------------------------------------------------------------
__global__ __launch_bounds__(256, 1) void k_xw2(const float* __restrict__ W2,
                                                const float* __restrict__ b2) {
    extern __shared__ double2 smx[];
    double2* w2s  = smx;                 // [32 f-pairs][256 g] = 128 KB
    double2* xdup = smx + 32 * 256;      // [16 t][64 f-pairs] = 16 KB
    float2* xdupf = (float2*)xdup;

    const int g = threadIdx.x;
    unsigned long long wr[64];
#pragma unroll
    for (int f = 0; f < 64; f++)
        wr[f] = pk2(W2[f * G4 + 2 * g], W2[f * G4 + 2 * g + 1]);
    for (int p = 0; p < 32; p++) {
        int fs = 64 + 2 * p;
        unsigned long long w0 = pk2(W2[fs * G4 + 2 * g], W2[fs * G4 + 2 * g + 1]);
        unsigned long long w1 = pk2(W2[(fs + 1) * G4 + 2 * g], W2[(fs + 1) * G4 + 2 * g + 1]);
        w2s[p * 256 + g] = make_double2(__longlong_as_double(w0), __longlong_as_double(w1));
    }
    const unsigned long long biasp = pk2(b2[2 * g], b2[2 * g + 1]);
    __syncthreads();

    const int nunits = Bsz * TB2;            // 8192
    float v[8];
#pragma unroll
    for (int j = 0; j < 8; j++) v[j] = 0.0f;
    {
        int unit = blockIdx.x;
        if (unit < nunits) {
            int b = unit / TB2, tb = unit % TB2;
            const float* src = &g_h1c[((size_t)b * CH + tb * 16) * Usz];
#pragma unroll
            for (int j = 0; j < 8; j++) v[j] = src[j * 256 + g];
        }
    }

    for (int unit = blockIdx.x; unit < nunits; unit += gridDim.x) {
#pragma unroll
        for (int j = 0; j < 8; j++)
            xdupf[j * 256 + g] = make_float2(v[j], v[j]);
        __syncthreads();

        int nu = unit + gridDim.x;
        if (nu < nunits) {
            int b = nu / TB2, tb = nu % TB2;
            const float* src = &g_h1c[((size_t)b * CH + tb * 16) * Usz];
#pragma unroll
            for (int j = 0; j < 8; j++) v[j] = src[j * 256 + g];
        }

        unsigned long long acc[16];
#pragma unroll
        for (int r = 0; r < 16; r++) acc[r] = biasp;
#pragma unroll 4
        for (int f2 = 0; f2 < 32; f2++) {
#pragma unroll
            for (int r = 0; r < 16; r++) {
                double2 d2 = xdup[r * 64 + f2];
                ffma2(acc[r], __double_as_longlong(d2.x), wr[2 * f2]);
                ffma2(acc[r], __double_as_longlong(d2.y), wr[2 * f2 + 1]);
            }
        }
#pragma unroll 4
        for (int p = 0; p < 32; p++) {
            double2 w = w2s[p * 256 + g];
            unsigned long long w0 = __double_as_longlong(w.x);
            unsigned long long w1 = __double_as_longlong(w.y);
#pragma unroll
            for (int r = 0; r < 16; r++) {
                double2 d2 = xdup[r * 64 + 32 + p];
                ffma2(acc[r], __double_as_longlong(d2.x), w0);
                ffma2(acc[r], __double_as_longlong(d2.y), w1);
            }
        }
        {
            int b = unit / TB2, tb = unit % TB2;
            float* dst = &g_xw2c[((size_t)b * CH + tb * 16) * G4];
#pragma unroll
            for (int r = 0; r < 16; r++)
                *(float2*)&dst[(size_t)r * G4 + 2 * g] = unpk2(acc[r]);
        }
        __syncthreads();
    }
}

// ---------------------------------------------------------------------------
// Recurrent kernel (round-12 exact structure). One CTA / batch element,
// 256 threads; thread g owns cols (2g, 2g+1).
// ---------------------------------------------------------------------------
#define RREC 80              // rows in registers
#define RPAIR (RREC / 2)     // 40 packed pairs
#define RSMM (Usz - RREC)    // 48 rows in smem
#define SPAIR (RSMM / 2)     // 24 packed pairs

template <bool LAYER1>
__global__ __launch_bounds__(256, 1) void lstm_rec(const float* __restrict__ Uw,
                                                   const float* __restrict__ Wd,
                                                   const float* __restrict__ bd,
                                                   float* __restrict__ out,
                                                   int first, int last) {
    extern __shared__ float sm[];
    float* ws   = sm;                          // SPAIR*1024 floats
    float* hbuf = sm + SPAIR * 1024;           // 128 floats
    float* zbuf = hbuf + Usz;                  // 512 floats

    const int g = threadIdx.x;                 // owns cols 2g, 2g+1
    const int b = blockIdx.x;
    const int gate = g >> 6;                   // 0:i 1:f 2:g(relu) 3:o
    const float* __restrict__ xw =
        (LAYER1 ? (const float*)g_xw1c : (const float*)g_xw2c) + (size_t)b * CH * G4;
    float* __restrict__ hs = LAYER1 ? g_h1s : g_h2s;
    float* __restrict__ cs = LAYER1 ? g_c1s : g_c2s;

    unsigned long long wrA[RPAIR], wrB[RPAIR];
#pragma unroll
    for (int p = 0; p < RPAIR; p++) {
        wrA[p] = pk2(Uw[(2 * p) * G4 + 2 * g],     Uw[(2 * p + 1) * G4 + 2 * g]);
        wrB[p] = pk2(Uw[(2 * p) * G4 + 2 * g + 1], Uw[(2 * p + 1) * G4 + 2 * g + 1]);
    }
    for (int i = g; i < SPAIR * 256; i += 256) {
        int p = i >> 8, q = i & 255;
        int r0 = RREC + 2 * p;
        ((float4*)ws)[i] = make_float4(Uw[r0 * G4 + 2 * q], Uw[(r0 + 1) * G4 + 2 * q],
                                       Uw[r0 * G4 + 2 * q + 1], Uw[(r0 + 1) * G4 + 2 * q + 1]);
    }

    float c = 0.0f;
    if (g < Usz) {
        hbuf[g] = first ? 0.0f : hs[b * Usz + g];
        if (!first) c = cs[b * Usz + g];
    }
    __syncthreads();

    float2 cur = *(const float2*)&xw[2 * g];   // tc = 0

    const double2* hb2 = (const double2*)hbuf;
    const double2* wsd = (const double2*)ws;

    for (int tc = 0; tc < CH; tc++) {
        float2 nxt = make_float2(0.0f, 0.0f);
        if (tc + 1 < CH)
            nxt = *(const float2*)&xw[(size_t)(tc + 1) * G4 + 2 * g];

        unsigned long long accA0 = 0ull, accA1 = 0ull, accB0 = 0ull, accB1 = 0ull;
#pragma unroll
        for (int k = 0; k < RPAIR / 2; k++) {
            double2 hd = hb2[k];
            unsigned long long h01 = __double_as_longlong(hd.x);
            unsigned long long h23 = __double_as_longlong(hd.y);
            ffma2(accA0, h01, wrA[2 * k]);
            ffma2(accB0, h01, wrB[2 * k]);
            ffma2(accA1, h23, wrA[2 * k + 1]);
            ffma2(accB1, h23, wrB[2 * k + 1]);
        }
#pragma unroll
        for (int k = 0; k < SPAIR / 2; k++) {
            double2 hd = hb2[RPAIR / 2 + k];
            unsigned long long h01 = __double_as_longlong(hd.x);
            unsigned long long h23 = __double_as_longlong(hd.y);
            double2 w0 = wsd[(2 * k) * 256 + g];
            double2 w1 = wsd[(2 * k + 1) * 256 + g];
            ffma2(accA0, h01, __double_as_longlong(w0.x));
            ffma2(accB0, h01, __double_as_longlong(w0.y));
            ffma2(accA1, h23, __double_as_longlong(w1.x));
            ffma2(accB1, h23, __double_as_longlong(w1.y));
        }
        float zA = cur.x + hsum2(add2(accA0, accA1));
        float zB = cur.y + hsum2(add2(accB0, accB1));
        if (gate == 2) { zA = fmaxf(zA, 0.0f); zB = fmaxf(zB, 0.0f); }
        else           { zA = sigmoidf(zA);    zB = sigmoidf(zB);    }
        *(float2*)&zbuf[2 * g] = make_float2(zA, zB);
        __syncthreads();

        if (g < Usz) {
            float ig = zbuf[g];
            float fg = zbuf[Usz + g];
            float gg = zbuf[2 * Usz + g];
            float og = zbuf[3 * Usz + g];
            c = fg * c + ig * gg;
            float h = og * fmaxf(c, 0.0f);
            hbuf[g] = h;
            if (LAYER1)
                g_h1c[((size_t)b * CH + tc) * Usz + g] = h;
        }
        __syncthreads();
        cur = nxt;
    }

    if (g < Usz) {
        hs[b * Usz + g] = hbuf[g];
        cs[b * Usz + g] = c;
    }

    if (!LAYER1 && last) {
        zbuf[g] = (g < Usz) ? hbuf[g] * Wd[g] : 0.0f;
        __syncthreads();
        if (g == 0) {
            float s = bd[0];
#pragma unroll 8
            for (int u = 0; u < Usz; u++) s += zbuf[u];
            out[b] = s;
        }
    }
}

// ---------------------------------------------------------------------------
extern "C" void kernel_launch(void* const* d_in, const int* in_sizes, int n_in,
                              void* d_out, int out_size) {
    const float* x  = (const float*)d_in[0];
    const float* W1 = (const float*)d_in[1];
    const float* U1 = (const float*)d_in[2];
    const float* b1 = (const float*)d_in[3];
    const float* W2 = (const float*)d_in[4];
    const float* U2 = (const float*)d_in[5];
    const float* b2 = (const float*)d_in[6];
    const float* Wd = (const float*)d_in[7];
    const float* bd = (const float*)d_in[8];
    float* out = (float*)d_out;

    const size_t sm_xw1 = (size_t)(XW1_FSMP * 256 + 8 * 32) * sizeof(double2);  // 52 KB
    const size_t sm_xw2 = (size_t)(32 * 256 + 16 * 64) * sizeof(double2);       // 144 KB
    const size_t sm_rec = (size_t)(SPAIR * 1024 + Usz + G4) * sizeof(float);    // ~101 KB

    (void)cudaFuncSetAttribute((const void*)k_xw1,
                         cudaFuncAttributeMaxDynamicSharedMemorySize, (int)sm_xw1);
    (void)cudaFuncSetAttribute((const void*)k_xw2,
                         cudaFuncAttributeMaxDynamicSharedMemorySize, (int)sm_xw2);
    (void)cudaFuncSetAttribute((const void*)lstm_rec<true>,
                         cudaFuncAttributeMaxDynamicSharedMemorySize, (int)sm_rec);
    (void)cudaFuncSetAttribute((const void*)lstm_rec<false>,
                         cudaFuncAttributeMaxDynamicSharedMemorySize, (int)sm_rec);

    for (int k = 0; k < NCH; k++) {
        const int first = (k == 0);
        const int last  = (k == NCH - 1);
        k_xw1<<<296, 256, sm_xw1>>>(x, W1, b1, k * CH);
        lstm_rec<true><<<Bsz, 256, sm_rec>>>(U1, Wd, bd, out, first, last);
        k_xw2<<<148, 256, sm_xw2>>>(W2, b2);
        lstm_rec<false><<<Bsz, 256, sm_rec>>>(U2, Wd, bd, out, first, last);
    }
}

// round 17
// speedup vs baseline: 1.3609x; 1.0141x over previous
#include <cuda_runtime.h>

#define Bsz 128
#define Tsz 2048
#define Fsz 64
#define Usz 128
#define G4  512          // 4*U
#define CH  1024         // time-chunk length
#define NCH (Tsz / CH)   // 2 chunks
#define TB1 (CH / 8)     // 128 xw1 t-blocks per chunk (8 t per unit)
#define TB2 (CH / 32)    // 32 xw2 t-blocks per chunk (32 t per unit)

// Chunked scratch, b-major layouts. ~580 MB total.
__device__ float g_xw1c[(size_t)Bsz * CH * G4];   // 256 MB: [b][tc][512]
__device__ float g_h1c [(size_t)Bsz * CH * Usz];  // 64 MB:  [b][tc][128]
__device__ float g_xw2c[(size_t)Bsz * CH * G4];   // 256 MB: [b][tc][512]
// Carried recurrent state (h,c per layer), [b][u]
__device__ float g_h1s[Bsz * Usz];
__device__ float g_c1s[Bsz * Usz];
__device__ float g_h2s[Bsz * Usz];
__device__ float g_c2s[Bsz * Usz];

__device__ __forceinline__ float sigmoidf(float x) {
    return __fdividef(1.0f, 1.0f + __expf(-x));
}

// ---- packed f32x2 helpers (Blackwell) -------------------------------------
__device__ __forceinline__ unsigned long long pk2(float lo, float hi) {
    unsigned long long r;
    asm("mov.b64 %0, {%1, %2};" : "=l"(r) : "f"(lo), "f"(hi));
    return r;
}
__device__ __forceinline__ void ffma2(unsigned long long& acc,
                                      unsigned long long a,
                                      unsigned long long b) {
    asm("fma.rn.f32x2 %0, %1, %2, %0;" : "+l"(acc) : "l"(a), "l"(b));
}
__device__ __forceinline__ float hsum2(unsigned long long a) {
    float lo, hi;
    asm("mov.b64 {%0, %1}, %2;" : "=f"(lo), "=f"(hi) : "l"(a));
    return lo + hi;
}
__device__ __forceinline__ unsigned long long add2(unsigned long long a,
                                                   unsigned long long b) {
    unsigned long long r;
    asm("add.rn.f32x2 %0, %1, %2;" : "=l"(r) : "l"(a), "l"(b));
    return r;
}
__device__ __forceinline__ float2 unpk2(unsigned long long a) {
    float lo, hi;
    asm("mov.b64 {%0, %1}, %2;" : "=f"(lo), "=f"(hi) : "l"(a));
    return make_float2(lo, hi);
}

// ---------------------------------------------------------------------------
// k_xw1 (f32x2): unchanged from round 16.
// ---------------------------------------------------------------------------
#define XW1_FREG 40                     // f rows in registers
#define XW1_FSMP ((Fsz - XW1_FREG) / 2) // 12 smem f-pairs

__global__ __launch_bounds__(256, 2) void k_xw1(const float* __restrict__ x,
                                                const float* __restrict__ W1,
                                                const float* __restrict__ b1,
                                                int t0) {
    extern __shared__ double2 sm1[];
    double2* w1s = sm1;                    // [12 f-pairs][256 g] = 48 KB
    double2* xs2 = sm1 + XW1_FSMP * 256;   // [8 t][32 f-pairs] = 4 KB
    float2* xs2f = (float2*)xs2;

    const int g = threadIdx.x;
    unsigned long long wr[XW1_FREG];
#pragma unroll
    for (int f = 0; f < XW1_FREG; f++)
        wr[f] = pk2(W1[f * G4 + 2 * g], W1[f * G4 + 2 * g + 1]);
    for (int p = 0; p < XW1_FSMP; p++) {
        int fs = XW1_FREG + 2 * p;
        unsigned long long w0 = pk2(W1[fs * G4 + 2 * g], W1[fs * G4 + 2 * g + 1]);
        unsigned long long w1 = pk2(W1[(fs + 1) * G4 + 2 * g], W1[(fs + 1) * G4 + 2 * g + 1]);
        w1s[p * 256 + g] = make_double2(__longlong_as_double(w0), __longlong_as_double(w1));
    }
    const unsigned long long biasp = pk2(b1[2 * g], b1[2 * g + 1]);
    __syncthreads();

    const int nunits = Bsz * TB1;            // 16384
    float v0 = 0.0f, v1 = 0.0f;
    {
        int unit = blockIdx.x;
        if (unit < nunits) {
            int b = unit / TB1, tb = unit % TB1;
            const float* src = &x[((size_t)b * Tsz + t0 + tb * 8) * Fsz];
            v0 = src[g];
            v1 = src[256 + g];
        }
    }

    for (int unit = blockIdx.x; unit < nunits; unit += gridDim.x) {
        xs2f[g]       = make_float2(v0, v0);
        xs2f[256 + g] = make_float2(v1, v1);
        __syncthreads();

        int nu = unit + gridDim.x;
        if (nu < nunits) {
            int b = nu / TB1, tb = nu % TB1;
            const float* src = &x[((size_t)b * Tsz + t0 + tb * 8) * Fsz];
            v0 = src[g];
            v1 = src[256 + g];
        }

        unsigned long long acc[8];
#pragma unroll
        for (int r = 0; r < 8; r++) acc[r] = biasp;
#pragma unroll 5
        for (int f2 = 0; f2 < XW1_FREG / 2; f2++) {
#pragma unroll
            for (int r = 0; r < 8; r++) {
                double2 d2 = xs2[r * 32 + f2];
                ffma2(acc[r], __double_as_longlong(d2.x), wr[2 * f2]);
                ffma2(acc[r], __double_as_longlong(d2.y), wr[2 * f2 + 1]);
            }
        }
#pragma unroll 4
        for (int p = 0; p < XW1_FSMP; p++) {
            double2 w = w1s[p * 256 + g];
            unsigned long long w0 = __double_as_longlong(w.x);
            unsigned long long w1 = __double_as_longlong(w.y);
#pragma unroll
            for (int r = 0; r < 8; r++) {
                double2 d2 = xs2[r * 32 + XW1_FREG / 2 + p];
                ffma2(acc[r], __double_as_longlong(d2.x), w0);
                ffma2(acc[r], __double_as_longlong(d2.y), w1);
            }
        }
        {
            int b = unit / TB1, tb = unit % TB1;
            float* dst = &g_xw1c[((size_t)b * CH + tb * 8) * G4];
#pragma unroll
            for (int r = 0; r < 8; r++)
                *(float2*)&dst[(size_t)r * G4 + 2 * g] = unpk2(acc[r]);
        }
        __syncthreads();
    }
}

// ---------------------------------------------------------------------------
// k_xw2 (f32x2): unit = (b, 32 consecutive t). 32 acc chains per thread so
// each smem weight read feeds 32 rows (weight-crossbar per output halves vs
// 16 rows). K=128: f 0..63 in regs, f 64..127 in smem (packed double2).
// h1 fill = one contiguous 16 KB read, prefetched one unit ahead.
// ---------------------------------------------------------------------------
__global__ __launch_bounds__(256, 1) void k_xw2(const float* __restrict__ W2,
                                                const float* __restrict__ b2) {
    extern __shared__ double2 smx[];
    double2* w2s  = smx;                 // [32 f-pairs][256 g] = 128 KB
    double2* xdup = smx + 32 * 256;      // [32 t][64 f-pairs] = 32 KB
    float2* xdupf = (float2*)xdup;

    const int g = threadIdx.x;
    unsigned long long wr[64];
#pragma unroll
    for (int f = 0; f < 64; f++)
        wr[f] = pk2(W2[f * G4 + 2 * g], W2[f * G4 + 2 * g + 1]);
    for (int p = 0; p < 32; p++) {
        int fs = 64 + 2 * p;
        unsigned long long w0 = pk2(W2[fs * G4 + 2 * g], W2[fs * G4 + 2 * g + 1]);
        unsigned long long w1 = pk2(W2[(fs + 1) * G4 + 2 * g], W2[(fs + 1) * G4 + 2 * g + 1]);
        w2s[p * 256 + g] = make_double2(__longlong_as_double(w0), __longlong_as_double(w1));
    }
    const unsigned long long biasp = pk2(b2[2 * g], b2[2 * g + 1]);
    __syncthreads();

    const int nunits = Bsz * TB2;            // 4096
    float v[16];
#pragma unroll
    for (int j = 0; j < 16; j++) v[j] = 0.0f;
    {
        int unit = blockIdx.x;
        if (unit < nunits) {
            int b = unit / TB2, tb = unit % TB2;
            const float* src = &g_h1c[((size_t)b * CH + tb * 32) * Usz];
#pragma unroll
            for (int j = 0; j < 16; j++) v[j] = src[j * 256 + g];
        }
    }

    for (int unit = blockIdx.x; unit < nunits; unit += gridDim.x) {
#pragma unroll
        for (int j = 0; j < 16; j++)
            xdupf[j * 256 + g] = make_float2(v[j], v[j]);
        __syncthreads();

        int nu = unit + gridDim.x;
        if (nu < nunits) {
            int b = nu / TB2, tb = nu % TB2;
            const float* src = &g_h1c[((size_t)b * CH + tb * 32) * Usz];
#pragma unroll
            for (int j = 0; j < 16; j++) v[j] = src[j * 256 + g];
        }

        unsigned long long acc[32];
#pragma unroll
        for (int r = 0; r < 32; r++) acc[r] = biasp;
        // f = 0..63 (register weights)
#pragma unroll 2
        for (int f2 = 0; f2 < 32; f2++) {
#pragma unroll
            for (int r = 0; r < 32; r++) {
                double2 d2 = xdup[r * 64 + f2];
                ffma2(acc[r], __double_as_longlong(d2.x), wr[2 * f2]);
                ffma2(acc[r], __double_as_longlong(d2.y), wr[2 * f2 + 1]);
            }
        }
        // f = 64..127 (smem weights)
#pragma unroll 2
        for (int p = 0; p < 32; p++) {
            double2 w = w2s[p * 256 + g];
            unsigned long long w0 = __double_as_longlong(w.x);
            unsigned long long w1 = __double_as_longlong(w.y);
#pragma unroll
            for (int r = 0; r < 32; r++) {
                double2 d2 = xdup[r * 64 + 32 + p];
                ffma2(acc[r], __double_as_longlong(d2.x), w0);
                ffma2(acc[r], __double_as_longlong(d2.y), w1);
            }
        }
        {
            int b = unit / TB2, tb = unit % TB2;
            float* dst = &g_xw2c[((size_t)b * CH + tb * 32) * G4];
#pragma unroll
            for (int r = 0; r < 32; r++)
                *(float2*)&dst[(size_t)r * G4 + 2 * g] = unpk2(acc[r]);
        }
        __syncthreads();
    }
}

// ---------------------------------------------------------------------------
// Recurrent kernel (round-12 exact structure). One CTA / batch element,
// 256 threads; thread g owns cols (2g, 2g+1).
// ---------------------------------------------------------------------------
#define RREC 80              // rows in registers
#define RPAIR (RREC / 2)     // 40 packed pairs
#define RSMM (Usz - RREC)    // 48 rows in smem
#define SPAIR (RSMM / 2)     // 24 packed pairs

template <bool LAYER1>
__global__ __launch_bounds__(256, 1) void lstm_rec(const float* __restrict__ Uw,
                                                   const float* __restrict__ Wd,
                                                   const float* __restrict__ bd,
                                                   float* __restrict__ out,
                                                   int first, int last) {
    extern __shared__ float sm[];
    float* ws   = sm;                          // SPAIR*1024 floats
    float* hbuf = sm + SPAIR * 1024;           // 128 floats
    float* zbuf = hbuf + Usz;                  // 512 floats

    const int g = threadIdx.x;                 // owns cols 2g, 2g+1
    const int b = blockIdx.x;
    const int gate = g >> 6;                   // 0:i 1:f 2:g(relu) 3:o
    const float* __restrict__ xw =
        (LAYER1 ? (const float*)g_xw1c : (const float*)g_xw2c) + (size_t)b * CH * G4;
    float* __restrict__ hs = LAYER1 ? g_h1s : g_h2s;
    float* __restrict__ cs = LAYER1 ? g_c1s : g_c2s;

    unsigned long long wrA[RPAIR], wrB[RPAIR];
#pragma unroll
    for (int p = 0; p < RPAIR; p++) {
        wrA[p] = pk2(Uw[(2 * p) * G4 + 2 * g],     Uw[(2 * p + 1) * G4 + 2 * g]);
        wrB[p] = pk2(Uw[(2 * p) * G4 + 2 * g + 1], Uw[(2 * p + 1) * G4 + 2 * g + 1]);
    }
    for (int i = g; i < SPAIR * 256; i += 256) {
        int p = i >> 8, q = i & 255;
        int r0 = RREC + 2 * p;
        ((float4*)ws)[i] = make_float4(Uw[r0 * G4 + 2 * q], Uw[(r0 + 1) * G4 + 2 * q],
                                       Uw[r0 * G4 + 2 * q + 1], Uw[(r0 + 1) * G4 + 2 * q + 1]);
    }

    float c = 0.0f;
    if (g < Usz) {
        hbuf[g] = first ? 0.0f : hs[b * Usz + g];
        if (!first) c = cs[b * Usz + g];
    }
    __syncthreads();

    float2 cur = *(const float2*)&xw[2 * g];   // tc = 0

    const double2* hb2 = (const double2*)hbuf;
    const double2* wsd = (const double2*)ws;

    for (int tc = 0; tc < CH; tc++) {
        float2 nxt = make_float2(0.0f, 0.0f);
        if (tc + 1 < CH)
            nxt = *(const float2*)&xw[(size_t)(tc + 1) * G4 + 2 * g];

        unsigned long long accA0 = 0ull, accA1 = 0ull, accB0 = 0ull, accB1 = 0ull;
#pragma unroll
        for (int k = 0; k < RPAIR / 2; k++) {
            double2 hd = hb2[k];
            unsigned long long h01 = __double_as_longlong(hd.x);
            unsigned long long h23 = __double_as_longlong(hd.y);
            ffma2(accA0, h01, wrA[2 * k]);
            ffma2(accB0, h01, wrB[2 * k]);
            ffma2(accA1, h23, wrA[2 * k + 1]);
            ffma2(accB1, h23, wrB[2 * k + 1]);
        }
#pragma unroll
        for (int k = 0; k < SPAIR / 2; k++) {
            double2 hd = hb2[RPAIR / 2 + k];
            unsigned long long h01 = __double_as_longlong(hd.x);
            unsigned long long h23 = __double_as_longlong(hd.y);
            double2 w0 = wsd[(2 * k) * 256 + g];
            double2 w1 = wsd[(2 * k + 1) * 256 + g];
            ffma2(accA0, h01, __double_as_longlong(w0.x));
            ffma2(accB0, h01, __double_as_longlong(w0.y));
            ffma2(accA1, h23, __double_as_longlong(w1.x));
            ffma2(accB1, h23, __double_as_longlong(w1.y));
        }
        float zA = cur.x + hsum2(add2(accA0, accA1));
        float zB = cur.y + hsum2(add2(accB0, accB1));
        if (gate == 2) { zA = fmaxf(zA, 0.0f); zB = fmaxf(zB, 0.0f); }
        else           { zA = sigmoidf(zA);    zB = sigmoidf(zB);    }
        *(float2*)&zbuf[2 * g] = make_float2(zA, zB);
        __syncthreads();

        if (g < Usz) {
            float ig = zbuf[g];
            float fg = zbuf[Usz + g];
            float gg = zbuf[2 * Usz + g];
            float og = zbuf[3 * Usz + g];
            c = fg * c + ig * gg;
            float h = og * fmaxf(c, 0.0f);
            hbuf[g] = h;
            if (LAYER1)
                g_h1c[((size_t)b * CH + tc) * Usz + g] = h;
        }
        __syncthreads();
        cur = nxt;
    }

    if (g < Usz) {
        hs[b * Usz + g] = hbuf[g];
        cs[b * Usz + g] = c;
    }

    if (!LAYER1 && last) {
        zbuf[g] = (g < Usz) ? hbuf[g] * Wd[g] : 0.0f;
        __syncthreads();
        if (g == 0) {
            float s = bd[0];
#pragma unroll 8
            for (int u = 0; u < Usz; u++) s += zbuf[u];
            out[b] = s;
        }
    }
}

// ---------------------------------------------------------------------------
extern "C" void kernel_launch(void* const* d_in, const int* in_sizes, int n_in,
                              void* d_out, int out_size) {
    const float* x  = (const float*)d_in[0];
    const float* W1 = (const float*)d_in[1];
    const float* U1 = (const float*)d_in[2];
    const float* b1 = (const float*)d_in[3];
    const float* W2 = (const float*)d_in[4];
    const float* U2 = (const float*)d_in[5];
    const float* b2 = (const float*)d_in[6];
    const float* Wd = (const float*)d_in[7];
    const float* bd = (const float*)d_in[8];
    float* out = (float*)d_out;

    const size_t sm_xw1 = (size_t)(XW1_FSMP * 256 + 8 * 32) * sizeof(double2);  // 52 KB
    const size_t sm_xw2 = (size_t)(32 * 256 + 32 * 64) * sizeof(double2);       // 160 KB
    const size_t sm_rec = (size_t)(SPAIR * 1024 + Usz + G4) * sizeof(float);    // ~101 KB

    (void)cudaFuncSetAttribute((const void*)k_xw1,
                         cudaFuncAttributeMaxDynamicSharedMemorySize, (int)sm_xw1);
    (void)cudaFuncSetAttribute((const void*)k_xw2,
                         cudaFuncAttributeMaxDynamicSharedMemorySize, (int)sm_xw2);
    (void)cudaFuncSetAttribute((const void*)lstm_rec<true>,
                         cudaFuncAttributeMaxDynamicSharedMemorySize, (int)sm_rec);
    (void)cudaFuncSetAttribute((const void*)lstm_rec<false>,
                         cudaFuncAttributeMaxDynamicSharedMemorySize, (int)sm_rec);

    for (int k = 0; k < NCH; k++) {
        const int first = (k == 0);
        const int last  = (k == NCH - 1);
        k_xw1<<<296, 256, sm_xw1>>>(x, W1, b1, k * CH);
        lstm_rec<true><<<Bsz, 256, sm_rec>>>(U1, Wd, bd, out, first, last);
        k_xw2<<<148, 256, sm_xw2>>>(W2, b2);
        lstm_rec<false><<<Bsz, 256, sm_rec>>>(U2, Wd, bd, out, first, last);
    }
}